// round 17
// baseline (speedup 1.0000x reference)
#include <cuda_runtime.h>
#include <cstddef>

#define BATCH    256
#define DATA_DIM 8192
#define NNZ      256
#define QK       64
#define EMB      63
#define NSUB     8
#define WTS      68
#define WPS      68    // padded stride for w staging segments (conflict-free)

typedef unsigned long long u64;

// Precomputed per-row projections of the embedding table (row 0 = padding row).
__device__ float4 g_Q0T[(DATA_DIM + 1) * 16];
__device__ float4 g_K0T[(DATA_DIM + 1) * 16];

// packed f32x2 FMA: acc = a*b + acc
__device__ __forceinline__ void fma2(u64& acc, u64 a, u64 b) {
    asm("fma.rn.f32x2 %0, %1, %2, %0;" : "+l"(acc) : "l"(a), "l"(b));
}
__device__ __forceinline__ float hsum2(u64 a) {
    return __uint_as_float((unsigned)a) + __uint_as_float((unsigned)(a >> 32));
}
__device__ __forceinline__ u64 pack2(float lo, float hi) {
    u64 r;
    asm("mov.b64 %0, {%1, %2};" : "=l"(r) : "f"(lo), "f"(hi));
    return r;
}

// ---------------------------------------------------------------------------
// Kernel P: 129 blocks x 64 table rows, one wave (R13, proven).
// Q0T[p][d] = bq[d] + sum_e embed[p][e] * Wq[d][e+1]   (same for K)
// ---------------------------------------------------------------------------
__global__ void __launch_bounds__(256)
precompute_kernel(const float* __restrict__ embed,
                  const float* __restrict__ Wq,
                  const float* __restrict__ bq,
                  const float* __restrict__ Wk,
                  const float* __restrict__ bk) {
    __shared__ __align__(16) float WqT[64 * WTS];
    __shared__ __align__(16) float WkT[64 * WTS];
    __shared__ __align__(16) float es[32][64];

    const int tid = threadIdx.x;
    for (int i = tid; i < 4096; i += 256) {
        int d = i >> 6, e = i & 63;
        WqT[e * WTS + d] = Wq[i];
        WkT[e * WTS + d] = Wk[i];
    }
    const int p0 = blockIdx.x * 64;
    const int rl = tid >> 4, d4 = tid & 15;
    const float4 bq4 = __ldg(reinterpret_cast<const float4*>(bq) + d4);
    const float4 bk4 = __ldg(reinterpret_cast<const float4*>(bk) + d4);

#pragma unroll
    for (int half = 0; half < 2; ++half) {
        const int ph = p0 + half * 32;
        __syncthreads();
        for (int i = tid; i < 32 * 63; i += 256) {
            int r = i / 63, e = i - r * 63;
            int p = ph + r;
            es[r][e] = (p <= DATA_DIM) ? embed[(size_t)p * EMB + e] : 0.0f;
        }
        __syncthreads();

#pragma unroll
        for (int grp = 0; grp < 2; ++grp) {
            const int r = grp * 16 + rl;
            const int p = ph + r;
            if (p <= DATA_DIM) {
                float4 aq = bq4, ak = bk4;
#pragma unroll 9
                for (int e = 0; e < EMB; ++e) {
                    float ev = es[r][e];
                    float4 wq = *reinterpret_cast<const float4*>(&WqT[(e + 1) * WTS + 4 * d4]);
                    float4 wk = *reinterpret_cast<const float4*>(&WkT[(e + 1) * WTS + 4 * d4]);
                    aq.x += ev * wq.x; aq.y += ev * wq.y; aq.z += ev * wq.z; aq.w += ev * wq.w;
                    ak.x += ev * wk.x; ak.y += ev * wk.y; ak.z += ev * wk.z; ak.w += ev * wk.w;
                }
                g_Q0T[(size_t)p * 16 + d4] = aq;
                g_K0T[(size_t)p * 16 + d4] = ak;
            }
        }
    }
}

// ---------------------------------------------------------------------------
// Kernel C: R14 base + in-warp s-computation.
// Warp w owns d in [8w,8w+8); lane = 4*dg + cc (dg = d within group, cc =
// j-quarter). m_d and S2 reduce with 2 in-warp shfls; s_d and the c1 partial
// complete BEFORE any barrier -> BAR A+B merged. 3 barriers/eval.
// i-ownership (q0 rows, qdot, wf tree, g) bit-identical to R14.
// ---------------------------------------------------------------------------
__global__ void __launch_bounds__(256, 1)
integrate_kernel(const float* __restrict__ t,
                 const float* __restrict__ x,
                 const float* __restrict__ Wq,
                 const float* __restrict__ Wk,
                 float* __restrict__ out) {
    __shared__ __align__(16) float wsh[4 * WPS];   // padded w staging
    __shared__ __align__(16) float ssh[QK];
    __shared__ __align__(16) float red2[8];        // per-warp w*f partials
    __shared__ __align__(16) float c1p[8];         // per-warp a.s partials
    __shared__ __align__(16) float val[NNZ];
    __shared__ int idx[NNZ];
    __shared__ int wscan[8];

    const int tid  = threadIdx.x;
    const int b    = blockIdx.x;
    const int lane = tid & 31;
    const int wid  = tid >> 5;

    // ---- Phase 0: zero this block's two output rows ----
    {
        float4 z = make_float4(0.f, 0.f, 0.f, 0.f);
        float4* o4 = reinterpret_cast<float4*>(out);
        for (int i = tid; i < 2048; i += 256) {
            o4[(size_t)b * 2048 + i] = z;
            o4[(size_t)(BATCH + b) * 2048 + i] = z;
        }
    }

    // ---- Phase 1: scan + order-preserving compaction ----
    float xr[32];
    {
        const float4* xrow4 = reinterpret_cast<const float4*>(x + (size_t)b * DATA_DIM) + tid * 8;
#pragma unroll
        for (int j = 0; j < 8; ++j) {
            float4 f = xrow4[j];
            xr[4 * j + 0] = f.x; xr[4 * j + 1] = f.y;
            xr[4 * j + 2] = f.z; xr[4 * j + 3] = f.w;
        }
    }
    if (tid < NNZ) { val[tid] = 0.0f; idx[tid] = 0; }

    int cnt = 0;
#pragma unroll
    for (int j = 0; j < 32; ++j) cnt += (xr[j] != 0.0f) ? 1 : 0;
    int inc = cnt;
#pragma unroll
    for (int o = 1; o < 32; o <<= 1) {
        int u = __shfl_up_sync(0xffffffffu, inc, o);
        if (lane >= o) inc += u;
    }
    if (lane == 31) wscan[wid] = inc;
    __syncthreads();
    int woff = 0;
#pragma unroll
    for (int wdx = 0; wdx < 8; ++wdx) woff += (wdx < wid) ? wscan[wdx] : 0;
    int o = woff + inc - cnt;
#pragma unroll
    for (int j = 0; j < 32; ++j) {
        float v = xr[j];
        if (v != 0.0f && o < NNZ) {
            val[o] = v;
            idx[o] = tid * 32 + j;
            ++o;
        }
    }
    __syncthreads();

    // ---- Phase 2: q0 row -> regs; k0 column -> regs via LDG ----
    const int p     = idx[tid] + 1;
    const float myv = val[tid];

    out[(size_t)b * DATA_DIM + (p - 1)] = myv;   // t=0 plane

    u64 q0p[32];   // my row of Q0 (64 floats as 32 packed pairs, sequential)
    {
        const ulonglong2* qrow = reinterpret_cast<const ulonglong2*>(g_Q0T + (size_t)p * 16);
#pragma unroll
        for (int i = 0; i < 16; ++i) {
            ulonglong2 v = qrow[i];
            q0p[2 * i] = v.x; q0p[2 * i + 1] = v.y;
        }
    }

    // s-role mapping: my d = dsg = 8*wid + (lane>>2); my j-quarter = ccm = lane&3
    const int dsg = 8 * wid + (lane >> 2);
    const int ccm = lane & 3;
    // i-identity mapping for staging: i = tid = 64*cc + dd
    const int dd = tid & 63, cc = tid >> 6;

    // k0 chunk: K0[p_j][dsg], j in [64*ccm, 64*ccm+64) -> 32 packed pairs
    u64 k0u[32];
    {
        const float* k0g = reinterpret_cast<const float*>(g_K0T);
        const int jb = ccm * 64;
#pragma unroll
        for (int j = 0; j < 32; ++j) {
            int pa = idx[jb + 2 * j] + 1;
            int pb = idx[jb + 2 * j + 1] + 1;
            float fa = __ldg(k0g + (size_t)pa * 64 + dsg);
            float fb = __ldg(k0g + (size_t)pb * 64 + dsg);
            k0u[j] = pack2(fa, fb);
        }
    }

    const float avd = Wq[dsg * 64];     // a_d
    const float bvd = Wk[dsg * 64];     // b_d

    const float dt = (t[1] - t[0]) * (1.0f / (float)NSUB);
    const ulonglong2* wvp = reinterpret_cast<const ulonglong2*>(wsh + ccm * WPS);
    const ulonglong2* svp = reinterpret_cast<const ulonglong2*>(ssh);

    // stage: bare STS by i-identity
    auto stage = [&](float w) {
        wsh[cc * WPS + dd] = w;
    };

    // dxdt(w) = w*(f - g);  s = S2*b + K0^T w  (in-warp);  f_i = (c1*w_i +
    // q0_i.s)/8;  c1 = a.s;  g = sum_j w_j f_j.  precondition: staged+synced.
    auto dxdt = [&](float w) -> float {
        // m_d and w^2 partials over my j-quarter (register FMAs, broadcast w)
        u64 a0 = 0ull, a1 = 0ull, s0 = 0ull, s1 = 0ull;
#pragma unroll
        for (int m = 0; m < 16; ++m) {
            ulonglong2 wv = wvp[m];
            fma2(a0, k0u[2 * m], wv.x);
            fma2(a1, k0u[2 * m + 1], wv.y);
            fma2(s0, wv.x, wv.x);
            fma2(s1, wv.y, wv.y);
        }
        float mp  = hsum2(a0) + hsum2(a1);
        float s2p = hsum2(s0) + hsum2(s1);
        // in-warp reduce over the 4 j-quarters of my d (lanes 4*dg + cc)
        mp  += __shfl_xor_sync(0xffffffffu, mp, 1);
        s2p += __shfl_xor_sync(0xffffffffu, s2p, 1);
        mp  += __shfl_xor_sync(0xffffffffu, mp, 2);
        s2p += __shfl_xor_sync(0xffffffffu, s2p, 2);
        float sv = fmaf(s2p, bvd, mp);             // s_d = S2*b_d + m_d
        if ((lane & 3) == 0) ssh[dsg] = sv;
        // c1 partial over my warp's 8 d's (cross-group shfls)
        float cp = avd * sv;
        cp += __shfl_xor_sync(0xffffffffu, cp, 4);
        cp += __shfl_xor_sync(0xffffffffu, cp, 8);
        cp += __shfl_xor_sync(0xffffffffu, cp, 16);
        if (lane == 0) c1p[wid] = cp;
        __syncthreads();                                   // BAR AB

        u64 q0 = 0ull, q1 = 0ull;
#pragma unroll
        for (int m = 0; m < 16; ++m) {
            ulonglong2 sv2 = svp[m];
            fma2(q0, q0p[2 * m], sv2.x);
            fma2(q1, q0p[2 * m + 1], sv2.y);
        }
        float qdot = hsum2(q0) + hsum2(q1);
        float4 cpa = *reinterpret_cast<const float4*>(&c1p[0]);
        float4 cpb = *reinterpret_cast<const float4*>(&c1p[4]);
        float c1 = (cpa.x + cpa.y) + (cpa.z + cpa.w) + (cpb.x + cpb.y) + (cpb.z + cpb.w);
        float f  = (c1 * w + qdot) * 0.125f;               // 1/sqrt(64)

        float wf = w * f;
#pragma unroll
        for (int o2 = 16; o2 > 0; o2 >>= 1) wf += __shfl_xor_sync(0xffffffffu, wf, o2);
        if (lane == 0) red2[wid] = wf;
        __syncthreads();                                   // BAR C
        float4 r2a = *reinterpret_cast<const float4*>(&red2[0]);
        float4 r2b = *reinterpret_cast<const float4*>(&red2[4]);
        float g = (r2a.x + r2a.y) + (r2a.z + r2a.w) + (r2b.x + r2b.y) + (r2b.z + r2b.w);

        return w * (f - g);
    };

    float vcur = myv;
    stage(vcur);
    __syncthreads();

    // ---- Phase 3: 8 RK4 substeps over [t0, t1] ----
    for (int stp = 0; stp < NSUB; ++stp) {
        float k1 = dxdt(vcur);
        float w2s = vcur + 0.5f * dt * k1;
        stage(w2s); __syncthreads();
        float k2 = dxdt(w2s);
        float w3s = vcur + 0.5f * dt * k2;
        stage(w3s); __syncthreads();
        float k3 = dxdt(w3s);
        float w4s = vcur + dt * k3;
        stage(w4s); __syncthreads();
        float k4 = dxdt(w4s);
        vcur += dt * (1.0f / 6.0f) * (k1 + 2.0f * k2 + 2.0f * k3 + k4);
        stage(vcur); __syncthreads();
    }

    // t=1 plane
    out[(size_t)BATCH * DATA_DIM + (size_t)b * DATA_DIM + (p - 1)] = vcur;
}

// ---------------------------------------------------------------------------
// kernel_launch
// ---------------------------------------------------------------------------
extern "C" void kernel_launch(void* const* d_in, const int* in_sizes, int n_in,
                              void* d_out, int out_size) {
    const float* t     = (const float*)d_in[0];
    const float* x     = (const float*)d_in[1];
    const float* embed = (const float*)d_in[2];
    const float* Wq    = (const float*)d_in[3];
    const float* bq    = (const float*)d_in[4];
    const float* Wk    = (const float*)d_in[5];
    const float* bk    = (const float*)d_in[6];
    float* out = (float*)d_out;

    precompute_kernel<<<(DATA_DIM + 1 + 63) / 64, 256>>>(embed, Wq, bq, Wk, bk);
    integrate_kernel<<<BATCH, 256>>>(t, x, Wq, Wk, out);
}